// round 6
// baseline (speedup 1.0000x reference)
#include <cuda_runtime.h>
#include <cuda_bf16.h>
#include <math.h>
#include <stdint.h>

#define B_  4
#define S_  2048
#define HID_ 1280
#define NH_ 16
#define NKV_ 4
#define HD_ 80
#define QKV_DIM_ 1920
#define M_TOT_ (B_ * S_)   // 8192
#define GQA_G_ (NH_ / NKV_)
#define NDP_ (HD_ / 2)     // 40 d-pairs

// ---------------- scratch ----------------
__device__ __align__(16) uint2 g_qp[(size_t)B_ * NH_ * NDP_ * S_];   // [bh][dpair][S] (hi,lo)
__device__ __align__(16) uint2 g_kp[(size_t)B_ * NKV_ * NDP_ * S_];  // [bkv][dpair][S]
__device__ float g_v[(size_t)B_ * NKV_ * S_ * HD_];                  // [bkv][S][HD] f32
__device__ __align__(16) uint2 g_vp[(size_t)B_ * NKV_ * (S_ / 2) * HD_]; // [bkv][spair][HD]
__device__ float g_o[(size_t)B_ * S_ * HID_];
__device__ float g_qscale[HD_];

// ---------------- bf16 split helpers ----------------
__device__ __forceinline__ unsigned short bf16b(float x) {
    return __bfloat16_as_ushort(__float2bfloat16_rn(x));
}
__device__ __forceinline__ void split_pack(float x0, float x1, uint32_t& hi, uint32_t& lo) {
    unsigned short h0 = bf16b(x0), h1 = bf16b(x1);
    hi = (uint32_t)h0 | ((uint32_t)h1 << 16);
    float f0 = __uint_as_float((uint32_t)h0 << 16);
    float f1 = __uint_as_float((uint32_t)h1 << 16);
    unsigned short l0 = bf16b(x0 - f0), l1 = bf16b(x1 - f1);
    lo = (uint32_t)l0 | ((uint32_t)l1 << 16);
}

__device__ __forceinline__ void mma_bf16(float* c, const uint32_t* a, const uint32_t* b) {
    asm volatile(
        "mma.sync.aligned.m16n8k16.row.col.f32.bf16.bf16.f32 "
        "{%0,%1,%2,%3}, {%4,%5,%6,%7}, {%8,%9}, {%0,%1,%2,%3};\n"
        : "+f"(c[0]), "+f"(c[1]), "+f"(c[2]), "+f"(c[3])
        : "r"(a[0]), "r"(a[1]), "r"(a[2]), "r"(a[3]), "r"(b[0]), "r"(b[1]));
}
__device__ __forceinline__ void mma3(float* c, const uint32_t* ah, const uint32_t* al,
                                     const uint32_t* bh, const uint32_t* bl) {
    mma_bf16(c, al, bh);
    mma_bf16(c, ah, bl);
    mma_bf16(c, ah, bh);
}

// ---------------- qscale ----------------
__global__ void qscale_kernel(const float* __restrict__ scaling) {
    int d = threadIdx.x;
    if (d < HD_) {
        float x = scaling[d];
        float sp = log1pf(expf(x));
        g_qscale[d] = 1.442695041f * rsqrtf((float)HD_) * sp;
    }
}

// ---------------- V pack: f32 [bkv][S][HD] -> uint2 [bkv][spair][HD] ----------------
__global__ void pack_v_kernel() {
    int idx = blockIdx.x * 256 + threadIdx.x;
    const int total = B_ * NKV_ * (S_ / 2) * HD_;
    if (idx >= total) return;
    int d = idx % HD_;
    int sp = (idx / HD_) % (S_ / 2);
    int bkv = idx / (HD_ * (S_ / 2));
    const float* vb = g_v + ((size_t)bkv * S_ + 2 * sp) * HD_ + d;
    uint32_t hi, lo;
    split_pack(vb[0], vb[HD_], hi, lo);
    g_vp[idx] = make_uint2(hi, lo);
}

// ---------------- GEMM epilogue scatter for MODE 0 ----------------
__device__ __forceinline__ void emit_qkv(int row, int col, float v0, float v1) {
    int b = row >> 11, s = row & (S_ - 1);
    uint32_t hi, lo;
    if (col < NH_ * HD_) {
        int h = col / HD_, d = col % HD_;   // col even -> d even
        v0 *= g_qscale[d]; v1 *= g_qscale[d + 1];
        split_pack(v0, v1, hi, lo);
        g_qp[((size_t)(b * NH_ + h) * NDP_ + (d >> 1)) * S_ + s] = make_uint2(hi, lo);
    } else if (col < NH_ * HD_ + NKV_ * HD_) {
        int cc = col - NH_ * HD_;
        int h = cc / HD_, d = cc % HD_;
        split_pack(v0, v1, hi, lo);
        g_kp[((size_t)(b * NKV_ + h) * NDP_ + (d >> 1)) * S_ + s] = make_uint2(hi, lo);
    } else {
        int cc = col - NH_ * HD_ - NKV_ * HD_;
        int h = cc / HD_, d = cc % HD_;
        float* vp = &g_v[((size_t)(b * NKV_ + h) * S_ + s) * HD_ + d];
        vp[0] = v0; vp[1] = v1;
    }
}

// ---------------- tensor-core GEMM: C[m,n] = sum_k A[m,k]*W[n,k] + bias[n] ------
// BM=BN=128, BK=32, 256 threads = 8 warps, warp tile 64x32.
// smem: interleaved (hi,lo) uint2, [kpair][m], stride 132 (==4 mod 16 -> conflict-free LDS.64)
#define GSTRU 132

template <int MODE>
__global__ __launch_bounds__(256) void gemm_tc(
    const float* __restrict__ A_arg, const float* __restrict__ W,
    const float* __restrict__ bias, float* __restrict__ C, int N, int K)
{
    const float* A = (MODE == 1) ? (const float*)g_o : A_arg;

    __shared__ uint2 Asm[16][GSTRU];
    __shared__ uint2 Bsm[16][GSTRU];

    int tid = threadIdx.x;
    int lane = tid & 31, wid = tid >> 5;
    int g = lane >> 2, tig = lane & 3;
    int wm = wid >> 2, wn = wid & 3;
    int bm = blockIdx.y * 128, bn = blockIdx.x * 128;

    float acc[4][4][4];
#pragma unroll
    for (int mi = 0; mi < 4; mi++)
#pragma unroll
        for (int ni = 0; ni < 4; ni++)
#pragma unroll
            for (int c = 0; c < 4; c++) acc[mi][ni][c] = 0.0f;

    int r0 = tid >> 2;
    int c4 = (tid & 3) * 4;

    float4 pa[4], pb[4];
    {
        const float* Ap = A + (size_t)bm * K;
        const float* Wp = W + (size_t)bn * K;
#pragma unroll
        for (int i = 0; i < 2; i++)
#pragma unroll
            for (int j = 0; j < 2; j++) {
                pa[i * 2 + j] = *(const float4*)&Ap[(size_t)(r0 + i * 64) * K + c4 + j * 16];
                pb[i * 2 + j] = *(const float4*)&Wp[(size_t)(r0 + i * 64) * K + c4 + j * 16];
            }
    }

    for (int k0 = 0; k0 < K; k0 += 32) {
#pragma unroll
        for (int i = 0; i < 2; i++) {
            int rr = r0 + i * 64;
#pragma unroll
            for (int j = 0; j < 2; j++) {
                int kp = (c4 >> 1) + j * 8;
                float4 va = pa[i * 2 + j], vb = pb[i * 2 + j];
                uint32_t hi, lo;
                split_pack(va.x, va.y, hi, lo); Asm[kp][rr] = make_uint2(hi, lo);
                split_pack(va.z, va.w, hi, lo); Asm[kp + 1][rr] = make_uint2(hi, lo);
                split_pack(vb.x, vb.y, hi, lo); Bsm[kp][rr] = make_uint2(hi, lo);
                split_pack(vb.z, vb.w, hi, lo); Bsm[kp + 1][rr] = make_uint2(hi, lo);
            }
        }
        __syncthreads();

        if (k0 + 32 < K) {
            const float* Ap = A + (size_t)bm * K + (k0 + 32);
            const float* Wp = W + (size_t)bn * K + (k0 + 32);
#pragma unroll
            for (int i = 0; i < 2; i++)
#pragma unroll
                for (int j = 0; j < 2; j++) {
                    pa[i * 2 + j] = *(const float4*)&Ap[(size_t)(r0 + i * 64) * K + c4 + j * 16];
                    pb[i * 2 + j] = *(const float4*)&Wp[(size_t)(r0 + i * 64) * K + c4 + j * 16];
                }
        }

#pragma unroll
        for (int ks = 0; ks < 2; ks++) {
            int kp0 = ks * 8;
            uint32_t afh[4][4], afl[4][4], bfh[4][2], bfl[4][2];
#pragma unroll
            for (int mi = 0; mi < 4; mi++) {
                int m0 = wm * 64 + mi * 16;
                uint2 q0v = Asm[kp0 + tig][m0 + g];
                uint2 q1v = Asm[kp0 + tig][m0 + g + 8];
                uint2 q2v = Asm[kp0 + tig + 4][m0 + g];
                uint2 q3v = Asm[kp0 + tig + 4][m0 + g + 8];
                afh[mi][0] = q0v.x; afl[mi][0] = q0v.y;
                afh[mi][1] = q1v.x; afl[mi][1] = q1v.y;
                afh[mi][2] = q2v.x; afl[mi][2] = q2v.y;
                afh[mi][3] = q3v.x; afl[mi][3] = q3v.y;
            }
#pragma unroll
            for (int ni = 0; ni < 4; ni++) {
                int n0 = wn * 32 + ni * 8;
                uint2 b0v = Bsm[kp0 + tig][n0 + g];
                uint2 b1v = Bsm[kp0 + tig + 4][n0 + g];
                bfh[ni][0] = b0v.x; bfl[ni][0] = b0v.y;
                bfh[ni][1] = b1v.x; bfl[ni][1] = b1v.y;
            }
#pragma unroll
            for (int mi = 0; mi < 4; mi++)
#pragma unroll
                for (int ni = 0; ni < 4; ni++)
                    mma3(acc[mi][ni], afh[mi], afl[mi], bfh[ni], bfl[ni]);
        }
        __syncthreads();
    }

    // epilogue
#pragma unroll
    for (int mi = 0; mi < 4; mi++) {
#pragma unroll
        for (int ni = 0; ni < 4; ni++) {
            int row0 = bm + wm * 64 + mi * 16 + g;
            int col0 = bn + wn * 32 + ni * 8 + tig * 2;
            float b0 = bias[col0], b1 = bias[col0 + 1];
            float v00 = acc[mi][ni][0] + b0, v01 = acc[mi][ni][1] + b1;
            float v10 = acc[mi][ni][2] + b0, v11 = acc[mi][ni][3] + b1;
            if (MODE == 0) {
                emit_qkv(row0, col0, v00, v01);
                emit_qkv(row0 + 8, col0, v10, v11);
            } else {
                C[(size_t)row0 * N + col0] = v00;
                C[(size_t)row0 * N + col0 + 1] = v01;
                C[(size_t)(row0 + 8) * N + col0] = v10;
                C[(size_t)(row0 + 8) * N + col0 + 1] = v11;
            }
        }
    }
}

// ---------------- causal flash attention, BR=128, BC=64, pre-split operands ----------------
#define BR_ 128
#define BC_ 64

struct AttnSmem {
    uint2 Qp[NDP_][132];      // [dpair][qrow]  (stride 132 == 4 mod 16)
    uint2 Kp[NDP_][68];       // [dpair][kvcol]
    uint2 Vp[BC_ / 2][84];    // [spair][d]
    float Ps[BR_][68];        // S then P (f32)
    float row_scale[BR_];
};

__global__ __launch_bounds__(256) void attn_kernel() {
    extern __shared__ char smem_raw[];
    AttnSmem& sm = *reinterpret_cast<AttnSmem*>(smem_raw);

    int tid = threadIdx.x;
    int lane = tid & 31, wid = tid >> 5;
    int g = lane >> 2, tig = lane & 3;
    int wm = wid >> 1, wn = wid & 1;      // wm 0..3 (32 rows), wn 0..1
    int qt = blockIdx.x;                  // 0..15
    int bh = blockIdx.y;
    int b = bh / NH_, h = bh % NH_;
    int kvh = h / GQA_G_;
    int bkv = b * NKV_ + kvh;
    int q0 = qt * BR_;

    // load pre-split Q tile: [dpair][128 cols]
    const uint2* qsrc = g_qp + (size_t)bh * NDP_ * S_;
    for (int i = tid; i < NDP_ * (BR_ / 2); i += 256) {
        int dp = i >> 6;          // /64
        int c2 = i & 63;
        *(float4*)&sm.Qp[dp][c2 * 2] =
            *(const float4*)&qsrc[(size_t)dp * S_ + q0 + c2 * 2];
    }

    float accO[2][5][4];
#pragma unroll
    for (int mi = 0; mi < 2; mi++)
#pragma unroll
        for (int ni = 0; ni < 5; ni++)
#pragma unroll
            for (int c = 0; c < 4; c++) accO[mi][ni][c] = 0.0f;

    int srow = tid >> 1, half = tid & 1;  // softmax: 2 threads per row, 32 cols each
    int qrow = q0 + srow;
    float mrow = -3.0e38f, lrow = 0.0f;

    const uint2* ksrc = g_kp + (size_t)bkv * NDP_ * S_;
    const uint2* vsrc = g_vp + (size_t)bkv * (S_ / 2) * HD_;

    int nkt = 2 * qt + 2;
    for (int kt = 0; kt < nkt; kt++) {
        int k0 = kt * BC_;
        __syncthreads();   // prev-iter consumers done (covers Q fill on iter 0)

        // K tile: [dpair][64 cols]
        for (int i = tid; i < NDP_ * (BC_ / 2); i += 256) {
            int dp = i >> 5;
            int c2 = i & 31;
            *(float4*)&sm.Kp[dp][c2 * 2] =
                *(const float4*)&ksrc[(size_t)dp * S_ + k0 + c2 * 2];
        }
        // V tile: [spair][80 d]
        for (int i = tid; i < (BC_ / 2) * (HD_ / 2); i += 256) {
            int sp = i / 40;
            int c2 = i % 40;
            *(float4*)&sm.Vp[sp][c2 * 2] =
                *(const float4*)&vsrc[(size_t)(k0 / 2 + sp) * HD_ + c2 * 2];
        }
        __syncthreads();

        // ---- S = Q K^T; warp tile 32x32 at (wm*32, wn*32) ----
        float sfrag[2][4][4];
#pragma unroll
        for (int mi = 0; mi < 2; mi++)
#pragma unroll
            for (int ni = 0; ni < 4; ni++)
#pragma unroll
                for (int c = 0; c < 4; c++) sfrag[mi][ni][c] = 0.0f;

#pragma unroll
        for (int ks = 0; ks < 5; ks++) {
            int kp0 = ks * 8;
            uint32_t ah[2][4], al[2][4];
#pragma unroll
            for (int mi = 0; mi < 2; mi++) {
                int m0 = wm * 32 + mi * 16;
                uint2 q0v = sm.Qp[kp0 + tig][m0 + g];
                uint2 q1v = sm.Qp[kp0 + tig][m0 + g + 8];
                uint2 q2v = sm.Qp[kp0 + tig + 4][m0 + g];
                uint2 q3v = sm.Qp[kp0 + tig + 4][m0 + g + 8];
                ah[mi][0] = q0v.x; al[mi][0] = q0v.y;
                ah[mi][1] = q1v.x; al[mi][1] = q1v.y;
                ah[mi][2] = q2v.x; al[mi][2] = q2v.y;
                ah[mi][3] = q3v.x; al[mi][3] = q3v.y;
            }
#pragma unroll
            for (int ni = 0; ni < 4; ni++) {
                int n0 = wn * 32 + ni * 8;
                uint2 b0v = sm.Kp[kp0 + tig][n0 + g];
                uint2 b1v = sm.Kp[kp0 + tig + 4][n0 + g];
                uint32_t bh2[2] = {b0v.x, b1v.x}, bl2[2] = {b0v.y, b1v.y};
#pragma unroll
                for (int mi = 0; mi < 2; mi++)
                    mma3(sfrag[mi][ni], ah[mi], al[mi], bh2, bl2);
            }
        }
        // store S
#pragma unroll
        for (int mi = 0; mi < 2; mi++) {
            int m0 = wm * 32 + mi * 16;
#pragma unroll
            for (int ni = 0; ni < 4; ni++) {
                int n0 = wn * 32 + ni * 8 + tig * 2;
                sm.Ps[m0 + g][n0]     = sfrag[mi][ni][0];
                sm.Ps[m0 + g][n0 + 1] = sfrag[mi][ni][1];
                sm.Ps[m0 + g + 8][n0]     = sfrag[mi][ni][2];
                sm.Ps[m0 + g + 8][n0 + 1] = sfrag[mi][ni][3];
            }
        }
        __syncthreads();

        // ---- online softmax: 2 threads per row, 32 cols each ----
        {
            bool diag = (kt >= 2 * qt);
            float sv[32];
            float mx = -3.0e38f;
#pragma unroll
            for (int c4i = 0; c4i < 8; c4i++) {
                float4 x4 = *(const float4*)&sm.Ps[srow][half * 32 + c4i * 4];
                float xs[4] = {x4.x, x4.y, x4.z, x4.w};
#pragma unroll
                for (int j = 0; j < 4; j++) {
                    int col = k0 + half * 32 + c4i * 4 + j;
                    float x = xs[j];
                    if (diag && col > qrow) x = -3.0e38f;
                    sv[c4i * 4 + j] = x;
                    mx = fmaxf(mx, x);
                }
            }
            mx = fmaxf(mx, __shfl_xor_sync(0xffffffffu, mx, 1));
            float mnew = fmaxf(mrow, mx);
            float alpha = __expf(mrow - mnew);
            float psum = 0.0f;
#pragma unroll
            for (int c4i = 0; c4i < 8; c4i++) {
                float4 p4;
                float p0 = __expf(sv[c4i * 4 + 0] - mnew);
                float p1 = __expf(sv[c4i * 4 + 1] - mnew);
                float p2 = __expf(sv[c4i * 4 + 2] - mnew);
                float p3 = __expf(sv[c4i * 4 + 3] - mnew);
                p4.x = p0; p4.y = p1; p4.z = p2; p4.w = p3;
                *(float4*)&sm.Ps[srow][half * 32 + c4i * 4] = p4;
                psum += p0 + p1 + p2 + p3;
            }
            psum += __shfl_xor_sync(0xffffffffu, psum, 1);
            lrow = lrow * alpha + psum;
            mrow = mnew;
            if (half == 0) sm.row_scale[srow] = alpha;
        }
        __syncthreads();

        // ---- rescale + O += P V; warp tile 32x40 at (wm*32, wn*40) ----
        {
#pragma unroll
            for (int mi = 0; mi < 2; mi++) {
                int m0 = wm * 32 + mi * 16;
                float a0 = sm.row_scale[m0 + g];
                float a1 = sm.row_scale[m0 + g + 8];
#pragma unroll
                for (int ni = 0; ni < 5; ni++) {
                    accO[mi][ni][0] *= a0; accO[mi][ni][1] *= a0;
                    accO[mi][ni][2] *= a1; accO[mi][ni][3] *= a1;
                }
            }
#pragma unroll
            for (int ks = 0; ks < 4; ks++) {
                int kp0 = ks * 8;
                int kv0 = ks * 16 + tig * 2;
                uint32_t ah[2][4], al[2][4];
#pragma unroll
                for (int mi = 0; mi < 2; mi++) {
                    int m0 = wm * 32 + mi * 16;
                    split_pack(sm.Ps[m0 + g][kv0],     sm.Ps[m0 + g][kv0 + 1],     ah[mi][0], al[mi][0]);
                    split_pack(sm.Ps[m0 + g + 8][kv0], sm.Ps[m0 + g + 8][kv0 + 1], ah[mi][1], al[mi][1]);
                    split_pack(sm.Ps[m0 + g][kv0 + 8], sm.Ps[m0 + g][kv0 + 9],     ah[mi][2], al[mi][2]);
                    split_pack(sm.Ps[m0 + g + 8][kv0 + 8], sm.Ps[m0 + g + 8][kv0 + 9], ah[mi][3], al[mi][3]);
                }
#pragma unroll
                for (int ni = 0; ni < 5; ni++) {
                    int n0 = wn * 40 + ni * 8;
                    uint2 b0v = sm.Vp[kp0 + tig][n0 + g];
                    uint2 b1v = sm.Vp[kp0 + tig + 4][n0 + g];
                    uint32_t bh2[2] = {b0v.x, b1v.x}, bl2[2] = {b0v.y, b1v.y};
#pragma unroll
                    for (int mi = 0; mi < 2; mi++)
                        mma3(accO[mi][ni], ah[mi], al[mi], bh2, bl2);
                }
            }
        }
    }

    // final normalization
    __syncthreads();
    if (half == 0) sm.row_scale[srow] = 1.0f / lrow;
    __syncthreads();
#pragma unroll
    for (int mi = 0; mi < 2; mi++) {
        int m0 = wm * 32 + mi * 16;
        float l0 = sm.row_scale[m0 + g];
        float l1 = sm.row_scale[m0 + g + 8];
#pragma unroll
        for (int ni = 0; ni < 5; ni++) {
            int cout = h * HD_ + wn * 40 + ni * 8 + tig * 2;
            int rr0 = q0 + m0 + g;
            int rr1 = rr0 + 8;
            float* o0 = g_o + ((size_t)(b * S_) + rr0) * HID_ + cout;
            float* o1 = g_o + ((size_t)(b * S_) + rr1) * HID_ + cout;
            o0[0] = accO[mi][ni][0] * l0; o0[1] = accO[mi][ni][1] * l0;
            o1[0] = accO[mi][ni][2] * l1; o1[1] = accO[mi][ni][3] * l1;
        }
    }
}

// ---------------- launch ----------------
extern "C" void kernel_launch(void* const* d_in, const int* in_sizes, int n_in,
                              void* d_out, int out_size) {
    const float* hs      = (const float*)d_in[0];
    const float* scaling = (const float*)d_in[2];
    const float* qkv_w   = (const float*)d_in[3];
    const float* qkv_b   = (const float*)d_in[4];
    const float* o_w     = (const float*)d_in[5];
    const float* o_b     = (const float*)d_in[6];
    float* out = (float*)d_out;

    const int attn_smem = (int)sizeof(AttnSmem);
    cudaFuncSetAttribute(attn_kernel, cudaFuncAttributeMaxDynamicSharedMemorySize, attn_smem);

    qscale_kernel<<<1, 128>>>(scaling);

    dim3 g1(QKV_DIM_ / 128, M_TOT_ / 128);
    gemm_tc<0><<<g1, 256>>>(hs, qkv_w, qkv_b, nullptr, QKV_DIM_, HID_);

    const int vtot = B_ * NKV_ * (S_ / 2) * HD_;
    pack_v_kernel<<<(vtot + 255) / 256, 256>>>();

    dim3 ga(S_ / BR_, B_ * NH_);
    attn_kernel<<<ga, 256, attn_smem>>>();

    dim3 g3(HID_ / 128, M_TOT_ / 128);
    gemm_tc<1><<<g3, 256>>>(nullptr, o_w, o_b, out, HID_, HID_);
}

// round 10
// speedup vs baseline: 1.1962x; 1.1962x over previous
#include <cuda_runtime.h>
#include <cuda_bf16.h>
#include <math.h>
#include <stdint.h>

#define B_  4
#define S_  2048
#define HID_ 1280
#define NH_ 16
#define NKV_ 4
#define HD_ 80
#define QKV_DIM_ 1920
#define M_TOT_ (B_ * S_)   // 8192
#define GQA_G_ (NH_ / NKV_)
#define NDP_ (HD_ / 2)     // 40 d-pairs

// ---------------- scratch ----------------
__device__ float g_q[(size_t)B_ * NH_ * S_ * HD_];                    // [bh][S][HD] f32 (scaled)
__device__ float g_k[(size_t)B_ * NKV_ * S_ * HD_];                   // [bkv][S][HD] f32
__device__ float g_v[(size_t)B_ * NKV_ * S_ * HD_];                   // [bkv][S][HD] f32
__device__ __align__(16) uint2 g_kp[(size_t)B_ * NKV_ * NDP_ * S_];   // [bkv][dpair][S] (hi,lo)
__device__ __align__(16) uint2 g_vp[(size_t)B_ * NKV_ * (S_ / 2) * HD_]; // [bkv][spair][HD]
__device__ float g_o[(size_t)B_ * S_ * HID_];
__device__ float g_qscale[HD_];

// ---------------- bf16 split helpers ----------------
__device__ __forceinline__ unsigned short bf16b(float x) {
    return __bfloat16_as_ushort(__float2bfloat16_rn(x));
}
__device__ __forceinline__ void split_pack(float x0, float x1, uint32_t& hi, uint32_t& lo) {
    unsigned short h0 = bf16b(x0), h1 = bf16b(x1);
    hi = (uint32_t)h0 | ((uint32_t)h1 << 16);
    float f0 = __uint_as_float((uint32_t)h0 << 16);
    float f1 = __uint_as_float((uint32_t)h1 << 16);
    unsigned short l0 = bf16b(x0 - f0), l1 = bf16b(x1 - f1);
    lo = (uint32_t)l0 | ((uint32_t)l1 << 16);
}

__device__ __forceinline__ void mma_bf16(float* c, const uint32_t* a, const uint32_t* b) {
    asm volatile(
        "mma.sync.aligned.m16n8k16.row.col.f32.bf16.bf16.f32 "
        "{%0,%1,%2,%3}, {%4,%5,%6,%7}, {%8,%9}, {%0,%1,%2,%3};\n"
        : "+f"(c[0]), "+f"(c[1]), "+f"(c[2]), "+f"(c[3])
        : "r"(a[0]), "r"(a[1]), "r"(a[2]), "r"(a[3]), "r"(b[0]), "r"(b[1]));
}
__device__ __forceinline__ void mma3(float* c, const uint32_t* ah, const uint32_t* al,
                                     const uint32_t* bh, const uint32_t* bl) {
    mma_bf16(c, al, bh);
    mma_bf16(c, ah, bl);
    mma_bf16(c, ah, bh);
}

// ---------------- qscale ----------------
__global__ void qscale_kernel(const float* __restrict__ scaling) {
    int d = threadIdx.x;
    if (d < HD_) {
        float x = scaling[d];
        float sp = log1pf(expf(x));
        g_qscale[d] = 1.442695041f * rsqrtf((float)HD_) * sp;
    }
}

// ---------------- K pack: f32 [bkv][S][HD] -> uint2 [bkv][dpair][S] (smem transpose) ----
__global__ __launch_bounds__(256) void pack_k_kernel() {
    __shared__ float tile[64][81];
    int bkv = blockIdx.y;
    int s0 = blockIdx.x * 64;
    const float* src = g_k + ((size_t)bkv * S_ + s0) * HD_;
    int tid = threadIdx.x;
    for (int i = tid; i < 64 * 20; i += 256) {
        int r = i / 20, c4 = (i % 20) * 4;
        float4 v = *(const float4*)&src[(size_t)r * HD_ + c4];
        tile[r][c4] = v.x; tile[r][c4 + 1] = v.y;
        tile[r][c4 + 2] = v.z; tile[r][c4 + 3] = v.w;
    }
    __syncthreads();
    for (int i = tid; i < NDP_ * 64; i += 256) {
        int dp = i >> 6, s = i & 63;
        uint32_t hi, lo;
        split_pack(tile[s][2 * dp], tile[s][2 * dp + 1], hi, lo);
        g_kp[((size_t)bkv * NDP_ + dp) * S_ + s0 + s] = make_uint2(hi, lo);
    }
}

// ---------------- V pack: f32 [bkv][S][HD] -> uint2 [bkv][spair][HD] ----------------
__global__ __launch_bounds__(256) void pack_v_kernel() {
    int idx = blockIdx.x * 256 + threadIdx.x;
    const int total = B_ * NKV_ * (S_ / 2) * HD_;
    if (idx >= total) return;
    int d = idx % HD_;
    int sp = (idx / HD_) % (S_ / 2);
    int bkv = idx / (HD_ * (S_ / 2));
    const float* vb = g_v + ((size_t)bkv * S_ + 2 * sp) * HD_ + d;
    uint32_t hi, lo;
    split_pack(vb[0], vb[HD_], hi, lo);
    g_vp[idx] = make_uint2(hi, lo);
}

// ---------------- MODE 0 epilogue scatter (coalesced f32, pairs) ----------------
__device__ __forceinline__ void emit_qkv(int row, int col, float v0, float v1) {
    int b = row >> 11, s = row & (S_ - 1);
    if (col < NH_ * HD_) {
        int h = col / HD_, d = col % HD_;
        float* p = &g_q[((size_t)(b * NH_ + h) * S_ + s) * HD_ + d];
        p[0] = v0 * g_qscale[d];
        p[1] = v1 * g_qscale[d + 1];
    } else if (col < NH_ * HD_ + NKV_ * HD_) {
        int cc = col - NH_ * HD_;
        int h = cc / HD_, d = cc % HD_;
        float* p = &g_k[((size_t)(b * NKV_ + h) * S_ + s) * HD_ + d];
        p[0] = v0; p[1] = v1;
    } else {
        int cc = col - NH_ * HD_ - NKV_ * HD_;
        int h = cc / HD_, d = cc % HD_;
        float* p = &g_v[((size_t)(b * NKV_ + h) * S_ + s) * HD_ + d];
        p[0] = v0; p[1] = v1;
    }
}

// ---------------- tensor-core GEMM: C[m,n] = sum_k A[m,k]*W[n,k] + bias[n] ------
#define GSTRU 132   // uint2 stride; 132 % 16 == 4 -> conflict-free LDS.64

template <int MODE>
__global__ __launch_bounds__(256) void gemm_tc(
    const float* __restrict__ A_arg, const float* __restrict__ W,
    const float* __restrict__ bias, float* __restrict__ C, int N, int K)
{
    const float* A = (MODE == 1) ? (const float*)g_o : A_arg;

    __shared__ uint2 Asm[16][GSTRU];
    __shared__ uint2 Bsm[16][GSTRU];

    int tid = threadIdx.x;
    int lane = tid & 31, wid = tid >> 5;
    int g = lane >> 2, tig = lane & 3;
    int wm = wid >> 2, wn = wid & 3;
    int bm = blockIdx.y * 128, bn = blockIdx.x * 128;

    float acc[4][4][4];
#pragma unroll
    for (int mi = 0; mi < 4; mi++)
#pragma unroll
        for (int ni = 0; ni < 4; ni++)
#pragma unroll
            for (int c = 0; c < 4; c++) acc[mi][ni][c] = 0.0f;

    int r0 = tid >> 2;
    int c4 = (tid & 3) * 4;

    float4 pa[4], pb[4];
    {
        const float* Ap = A + (size_t)bm * K;
        const float* Wp = W + (size_t)bn * K;
#pragma unroll
        for (int i = 0; i < 2; i++)
#pragma unroll
            for (int j = 0; j < 2; j++) {
                pa[i * 2 + j] = *(const float4*)&Ap[(size_t)(r0 + i * 64) * K + c4 + j * 16];
                pb[i * 2 + j] = *(const float4*)&Wp[(size_t)(r0 + i * 64) * K + c4 + j * 16];
            }
    }

    for (int k0 = 0; k0 < K; k0 += 32) {
#pragma unroll
        for (int i = 0; i < 2; i++) {
            int rr = r0 + i * 64;
#pragma unroll
            for (int j = 0; j < 2; j++) {
                int kp = (c4 >> 1) + j * 8;
                float4 va = pa[i * 2 + j], vb = pb[i * 2 + j];
                uint32_t hi, lo;
                split_pack(va.x, va.y, hi, lo); Asm[kp][rr] = make_uint2(hi, lo);
                split_pack(va.z, va.w, hi, lo); Asm[kp + 1][rr] = make_uint2(hi, lo);
                split_pack(vb.x, vb.y, hi, lo); Bsm[kp][rr] = make_uint2(hi, lo);
                split_pack(vb.z, vb.w, hi, lo); Bsm[kp + 1][rr] = make_uint2(hi, lo);
            }
        }
        __syncthreads();

        if (k0 + 32 < K) {
            const float* Ap = A + (size_t)bm * K + (k0 + 32);
            const float* Wp = W + (size_t)bn * K + (k0 + 32);
#pragma unroll
            for (int i = 0; i < 2; i++)
#pragma unroll
                for (int j = 0; j < 2; j++) {
                    pa[i * 2 + j] = *(const float4*)&Ap[(size_t)(r0 + i * 64) * K + c4 + j * 16];
                    pb[i * 2 + j] = *(const float4*)&Wp[(size_t)(r0 + i * 64) * K + c4 + j * 16];
                }
        }

#pragma unroll
        for (int ks = 0; ks < 2; ks++) {
            int kp0 = ks * 8;
            uint32_t afh[4][4], afl[4][4], bfh[4][2], bfl[4][2];
#pragma unroll
            for (int mi = 0; mi < 4; mi++) {
                int m0 = wm * 64 + mi * 16;
                uint2 q0v = Asm[kp0 + tig][m0 + g];
                uint2 q1v = Asm[kp0 + tig][m0 + g + 8];
                uint2 q2v = Asm[kp0 + tig + 4][m0 + g];
                uint2 q3v = Asm[kp0 + tig + 4][m0 + g + 8];
                afh[mi][0] = q0v.x; afl[mi][0] = q0v.y;
                afh[mi][1] = q1v.x; afl[mi][1] = q1v.y;
                afh[mi][2] = q2v.x; afl[mi][2] = q2v.y;
                afh[mi][3] = q3v.x; afl[mi][3] = q3v.y;
            }
#pragma unroll
            for (int ni = 0; ni < 4; ni++) {
                int n0 = wn * 32 + ni * 8;
                uint2 b0v = Bsm[kp0 + tig][n0 + g];
                uint2 b1v = Bsm[kp0 + tig + 4][n0 + g];
                bfh[ni][0] = b0v.x; bfl[ni][0] = b0v.y;
                bfh[ni][1] = b1v.x; bfl[ni][1] = b1v.y;
            }
#pragma unroll
            for (int mi = 0; mi < 4; mi++)
#pragma unroll
                for (int ni = 0; ni < 4; ni++)
                    mma3(acc[mi][ni], afh[mi], afl[mi], bfh[ni], bfl[ni]);
        }
        __syncthreads();
    }

#pragma unroll
    for (int mi = 0; mi < 4; mi++) {
#pragma unroll
        for (int ni = 0; ni < 4; ni++) {
            int row0 = bm + wm * 64 + mi * 16 + g;
            int col0 = bn + wn * 32 + ni * 8 + tig * 2;
            float b0 = bias[col0], b1 = bias[col0 + 1];
            float v00 = acc[mi][ni][0] + b0, v01 = acc[mi][ni][1] + b1;
            float v10 = acc[mi][ni][2] + b0, v11 = acc[mi][ni][3] + b1;
            if (MODE == 0) {
                emit_qkv(row0, col0, v00, v01);
                emit_qkv(row0 + 8, col0, v10, v11);
            } else {
                C[(size_t)row0 * N + col0] = v00;
                C[(size_t)row0 * N + col0 + 1] = v01;
                C[(size_t)(row0 + 8) * N + col0] = v10;
                C[(size_t)(row0 + 8) * N + col0 + 1] = v11;
            }
        }
    }
}

// ---------------- register-flash causal attention, BR=BC=64 ----------------
#define BR_ 64
#define BC_ 64

struct AttnSmem {
    uint2 Qp[NDP_][68];        // [dpair][qrow]   (68 % 16 == 4 -> conflict-free)
    uint2 Kp[NDP_][68];        // [dpair][kvcol]
    uint2 Vp[BC_ / 2][84];     // [spair][d]      (84 % 16 == 4)
    float redM[2][BR_];        // per-warp-half row max
    float redS[2][BR_];        // per-warp-half row sum
    float Obuf[BR_][HD_];      // final cross-warp O merge
};

__global__ __launch_bounds__(256, 2) void attn_kernel() {
    extern __shared__ char smem_raw[];
    AttnSmem& sm = *reinterpret_cast<AttnSmem*>(smem_raw);

    int tid = threadIdx.x;
    int lane = tid & 31, wid = tid >> 5;
    int g = lane >> 2, tig = lane & 3;
    int wm = wid >> 1, wn = wid & 1;      // wm 0..3 (16 rows), wn 0..1 (k-split for PV, n-split for QK)
    int qt = gridDim.x - 1 - blockIdx.x;  // long blocks first
    int bh = blockIdx.y;
    int b = bh / NH_, h = bh % NH_;
    int kvh = h / GQA_G_;
    int bkv = b * NKV_ + kvh;
    int q0 = qt * BR_;

    // Q fill: split f32 -> packed smem (once per block)
    const float* qptr = g_q + ((size_t)bh * S_ + q0) * HD_;
    for (int i = tid; i < BR_ * (HD_ / 4); i += 256) {
        int r = i / 20, c4 = (i % 20) * 4;
        float4 qv = *(const float4*)&qptr[(size_t)r * HD_ + c4];
        uint32_t hi, lo;
        split_pack(qv.x, qv.y, hi, lo); sm.Qp[c4 >> 1][r] = make_uint2(hi, lo);
        split_pack(qv.z, qv.w, hi, lo); sm.Qp[(c4 >> 1) + 1][r] = make_uint2(hi, lo);
    }

    float accO[10][4];
#pragma unroll
    for (int ni = 0; ni < 10; ni++)
#pragma unroll
        for (int c = 0; c < 4; c++) accO[ni][c] = 0.0f;

    int row0 = wm * 16 + g, row1 = row0 + 8;   // this thread's two rows (local)
    float m0r = -3.0e38f, m1r = -3.0e38f, l0r = 0.0f, l1r = 0.0f;

    const uint2* ksrc = g_kp + (size_t)bkv * NDP_ * S_;
    const uint2* vsrc = g_vp + (size_t)bkv * (S_ / 2) * HD_;

    for (int kt = 0; kt <= qt; kt++) {
        int k0 = kt * BC_;
        __syncthreads();   // prev-iter PV readers of Kp/Vp done (covers Q fill on iter 0)

        for (int i = tid; i < NDP_ * (BC_ / 2); i += 256) {   // K: pure copy
            int dp = i >> 5, c2 = i & 31;
            *(float4*)&sm.Kp[dp][c2 * 2] =
                *(const float4*)&ksrc[(size_t)dp * S_ + k0 + c2 * 2];
        }
        for (int i = tid; i < (BC_ / 2) * (HD_ / 2); i += 256) {  // V: pure copy
            int sp = i / 40, c2 = i % 40;
            *(float4*)&sm.Vp[sp][c2 * 2] =
                *(const float4*)&vsrc[(size_t)(k0 / 2 + sp) * HD_ + c2 * 2];
        }
        __syncthreads();

        // ---- S = Q K^T; warp tile 16x32 at (wm*16, wn*32); stays in registers ----
        float sf[4][4];
#pragma unroll
        for (int ni = 0; ni < 4; ni++)
#pragma unroll
            for (int c = 0; c < 4; c++) sf[ni][c] = 0.0f;

#pragma unroll
        for (int ks = 0; ks < 5; ks++) {
            int kp0 = ks * 8;
            int m0 = wm * 16;
            uint2 q0v = sm.Qp[kp0 + tig][m0 + g];
            uint2 q1v = sm.Qp[kp0 + tig][m0 + g + 8];
            uint2 q2v = sm.Qp[kp0 + tig + 4][m0 + g];
            uint2 q3v = sm.Qp[kp0 + tig + 4][m0 + g + 8];
            uint32_t ah[4] = {q0v.x, q1v.x, q2v.x, q3v.x};
            uint32_t al[4] = {q0v.y, q1v.y, q2v.y, q3v.y};
#pragma unroll
            for (int ni = 0; ni < 4; ni++) {
                int n0 = wn * 32 + ni * 8;
                uint2 b0v = sm.Kp[kp0 + tig][n0 + g];
                uint2 b1v = sm.Kp[kp0 + tig + 4][n0 + g];
                uint32_t bh2[2] = {b0v.x, b1v.x}, bl2[2] = {b0v.y, b1v.y};
                mma3(sf[ni], ah, al, bh2, bl2);
            }
        }

        // ---- causal mask on diagonal tile ----
        if (kt == qt) {
#pragma unroll
            for (int ni = 0; ni < 4; ni++) {
                int nb = wn * 32 + ni * 8 + 2 * tig;
                if (nb > row0)     sf[ni][0] = -3.0e38f;
                if (nb + 1 > row0) sf[ni][1] = -3.0e38f;
                if (nb > row1)     sf[ni][2] = -3.0e38f;
                if (nb + 1 > row1) sf[ni][3] = -3.0e38f;
            }
        }

        // ---- online softmax on fragments ----
        float pm0 = -3.0e38f, pm1 = -3.0e38f;
#pragma unroll
        for (int ni = 0; ni < 4; ni++) {
            pm0 = fmaxf(pm0, fmaxf(sf[ni][0], sf[ni][1]));
            pm1 = fmaxf(pm1, fmaxf(sf[ni][2], sf[ni][3]));
        }
        pm0 = fmaxf(pm0, __shfl_xor_sync(0xffffffffu, pm0, 1));
        pm0 = fmaxf(pm0, __shfl_xor_sync(0xffffffffu, pm0, 2));
        pm1 = fmaxf(pm1, __shfl_xor_sync(0xffffffffu, pm1, 1));
        pm1 = fmaxf(pm1, __shfl_xor_sync(0xffffffffu, pm1, 2));
        if (tig == 0) { sm.redM[wn][row0] = pm0; sm.redM[wn][row1] = pm1; }
        __syncthreads();
        float t0 = fmaxf(sm.redM[0][row0], sm.redM[1][row0]);
        float t1 = fmaxf(sm.redM[0][row1], sm.redM[1][row1]);
        float mn0 = fmaxf(m0r, t0), mn1 = fmaxf(m1r, t1);
        float a0 = __expf(m0r - mn0), a1 = __expf(m1r - mn1);
        m0r = mn0; m1r = mn1;

        float ps0 = 0.0f, ps1 = 0.0f;
#pragma unroll
        for (int ni = 0; ni < 4; ni++) {
            sf[ni][0] = __expf(sf[ni][0] - mn0);
            sf[ni][1] = __expf(sf[ni][1] - mn0);
            sf[ni][2] = __expf(sf[ni][2] - mn1);
            sf[ni][3] = __expf(sf[ni][3] - mn1);
            ps0 += sf[ni][0] + sf[ni][1];
            ps1 += sf[ni][2] + sf[ni][3];
        }
        ps0 += __shfl_xor_sync(0xffffffffu, ps0, 1);
        ps0 += __shfl_xor_sync(0xffffffffu, ps0, 2);
        ps1 += __shfl_xor_sync(0xffffffffu, ps1, 1);
        ps1 += __shfl_xor_sync(0xffffffffu, ps1, 2);
        if (tig == 0) { sm.redS[wn][row0] = ps0; sm.redS[wn][row1] = ps1; }
        __syncthreads();
        l0r = l0r * a0 + sm.redS[0][row0] + sm.redS[1][row0];
        l1r = l1r * a1 + sm.redS[0][row1] + sm.redS[1][row1];

        // ---- rescale accO + O_partial += P V over this warp's 32 kv cols ----
#pragma unroll
        for (int ni = 0; ni < 10; ni++) {
            accO[ni][0] *= a0; accO[ni][1] *= a0;
            accO[ni][2] *= a1; accO[ni][3] *= a1;
        }
#pragma unroll
        for (int kc = 0; kc < 2; kc++) {
            uint32_t ah[4], al[4];
            split_pack(sf[2 * kc][0],     sf[2 * kc][1],     ah[0], al[0]);
            split_pack(sf[2 * kc][2],     sf[2 * kc][3],     ah[1], al[1]);
            split_pack(sf[2 * kc + 1][0], sf[2 * kc + 1][1], ah[2], al[2]);
            split_pack(sf[2 * kc + 1][2], sf[2 * kc + 1][3], ah[3], al[3]);
            int kb = wn * 16 + kc * 8;
#pragma unroll
            for (int ni = 0; ni < 10; ni++) {
                uint2 b0v = sm.Vp[kb + tig][ni * 8 + g];
                uint2 b1v = sm.Vp[kb + tig + 4][ni * 8 + g];
                uint32_t bh2[2] = {b0v.x, b1v.x}, bl2[2] = {b0v.y, b1v.y};
                mma3(accO[ni], ah, al, bh2, bl2);
            }
        }
    }

    // ---- merge the two k-half partial O's, normalize, write ----
    __syncthreads();
    if (wn == 1) {
#pragma unroll
        for (int ni = 0; ni < 10; ni++) {
            int d = ni * 8 + 2 * tig;
            sm.Obuf[row0][d] = accO[ni][0]; sm.Obuf[row0][d + 1] = accO[ni][1];
            sm.Obuf[row1][d] = accO[ni][2]; sm.Obuf[row1][d + 1] = accO[ni][3];
        }
    }
    __syncthreads();
    if (wn == 0) {
        float li0 = 1.0f / l0r, li1 = 1.0f / l1r;
        float* o0 = g_o + ((size_t)(b * S_) + q0 + row0) * HID_ + h * HD_;
        float* o1 = g_o + ((size_t)(b * S_) + q0 + row1) * HID_ + h * HD_;
#pragma unroll
        for (int ni = 0; ni < 10; ni++) {
            int d = ni * 8 + 2 * tig;
            o0[d]     = (accO[ni][0] + sm.Obuf[row0][d])     * li0;
            o0[d + 1] = (accO[ni][1] + sm.Obuf[row0][d + 1]) * li0;
            o1[d]     = (accO[ni][2] + sm.Obuf[row1][d])     * li1;
            o1[d + 1] = (accO[ni][3] + sm.Obuf[row1][d + 1]) * li1;
        }
    }
}

// ---------------- launch ----------------
extern "C" void kernel_launch(void* const* d_in, const int* in_sizes, int n_in,
                              void* d_out, int out_size) {
    const float* hs      = (const float*)d_in[0];
    const float* scaling = (const float*)d_in[2];
    const float* qkv_w   = (const float*)d_in[3];
    const float* qkv_b   = (const float*)d_in[4];
    const float* o_w     = (const float*)d_in[5];
    const float* o_b     = (const float*)d_in[6];
    float* out = (float*)d_out;

    const int attn_smem = (int)sizeof(AttnSmem);
    cudaFuncSetAttribute(attn_kernel, cudaFuncAttributeMaxDynamicSharedMemorySize, attn_smem);

    qscale_kernel<<<1, 128>>>(scaling);

    dim3 g1(QKV_DIM_ / 128, M_TOT_ / 128);
    gemm_tc<0><<<g1, 256>>>(hs, qkv_w, qkv_b, nullptr, QKV_DIM_, HID_);

    dim3 gk(S_ / 64, B_ * NKV_);
    pack_k_kernel<<<gk, 256>>>();
    const int vtot = B_ * NKV_ * (S_ / 2) * HD_;
    pack_v_kernel<<<(vtot + 255) / 256, 256>>>();

    dim3 ga(S_ / BR_, B_ * NH_);
    attn_kernel<<<ga, 256, attn_smem>>>();

    dim3 g3(HID_ / 128, M_TOT_ / 128);
    gemm_tc<1><<<g3, 256>>>(nullptr, o_w, o_b, out, HID_, HID_);
}

// round 11
// speedup vs baseline: 1.2858x; 1.0749x over previous
#include <cuda_runtime.h>
#include <cuda_bf16.h>
#include <math.h>
#include <stdint.h>

#define B_  4
#define S_  2048
#define HID_ 1280
#define NH_ 16
#define NKV_ 4
#define HD_ 80
#define QKV_DIM_ 1920
#define M_TOT_ (B_ * S_)   // 8192
#define GQA_G_ (NH_ / NKV_)
#define NDP_ (HD_ / 2)     // 40 d-pairs

// ---------------- scratch ----------------
__device__ float g_q[(size_t)B_ * NH_ * S_ * HD_];                    // [bh][S][HD] f32 (scaled)
__device__ float g_k[(size_t)B_ * NKV_ * S_ * HD_];                   // [bkv][S][HD] f32
__device__ float g_v[(size_t)B_ * NKV_ * S_ * HD_];                   // [bkv][S][HD] f32
__device__ __align__(16) uint2 g_kp[(size_t)B_ * NKV_ * NDP_ * S_];   // [bkv][dpair][S] (hi,lo)
__device__ __align__(16) uint2 g_vp[(size_t)B_ * NKV_ * (S_ / 2) * HD_]; // [bkv][spair][HD]
__device__ float g_o[(size_t)B_ * S_ * HID_];
__device__ float g_qscale[HD_];

// ---------------- bf16 split helpers ----------------
__device__ __forceinline__ unsigned short bf16b(float x) {
    return __bfloat16_as_ushort(__float2bfloat16_rn(x));
}
__device__ __forceinline__ void split_pack(float x0, float x1, uint32_t& hi, uint32_t& lo) {
    unsigned short h0 = bf16b(x0), h1 = bf16b(x1);
    hi = (uint32_t)h0 | ((uint32_t)h1 << 16);
    float f0 = __uint_as_float((uint32_t)h0 << 16);
    float f1 = __uint_as_float((uint32_t)h1 << 16);
    unsigned short l0 = bf16b(x0 - f0), l1 = bf16b(x1 - f1);
    lo = (uint32_t)l0 | ((uint32_t)l1 << 16);
}

__device__ __forceinline__ void mma_bf16(float* c, const uint32_t* a, const uint32_t* b) {
    asm volatile(
        "mma.sync.aligned.m16n8k16.row.col.f32.bf16.bf16.f32 "
        "{%0,%1,%2,%3}, {%4,%5,%6,%7}, {%8,%9}, {%0,%1,%2,%3};\n"
        : "+f"(c[0]), "+f"(c[1]), "+f"(c[2]), "+f"(c[3])
        : "r"(a[0]), "r"(a[1]), "r"(a[2]), "r"(a[3]), "r"(b[0]), "r"(b[1]));
}
__device__ __forceinline__ void mma3(float* c, const uint32_t* ah, const uint32_t* al,
                                     const uint32_t* bh, const uint32_t* bl) {
    mma_bf16(c, al, bh);
    mma_bf16(c, ah, bl);
    mma_bf16(c, ah, bh);
}

// ---------------- qscale ----------------
__global__ void qscale_kernel(const float* __restrict__ scaling) {
    int d = threadIdx.x;
    if (d < HD_) {
        float x = scaling[d];
        float sp = log1pf(expf(x));
        g_qscale[d] = 1.442695041f * rsqrtf((float)HD_) * sp;
    }
}

// ---------------- K pack: f32 [bkv][S][HD] -> uint2 [bkv][dpair][S] (smem transpose) ----
__global__ __launch_bounds__(256) void pack_k_kernel() {
    __shared__ float tile[64][81];
    int bkv = blockIdx.y;
    int s0 = blockIdx.x * 64;
    const float* src = g_k + ((size_t)bkv * S_ + s0) * HD_;
    int tid = threadIdx.x;
    for (int i = tid; i < 64 * 20; i += 256) {
        int r = i / 20, c4 = (i % 20) * 4;
        float4 v = *(const float4*)&src[(size_t)r * HD_ + c4];
        tile[r][c4] = v.x; tile[r][c4 + 1] = v.y;
        tile[r][c4 + 2] = v.z; tile[r][c4 + 3] = v.w;
    }
    __syncthreads();
    for (int i = tid; i < NDP_ * 64; i += 256) {
        int dp = i >> 6, s = i & 63;
        uint32_t hi, lo;
        split_pack(tile[s][2 * dp], tile[s][2 * dp + 1], hi, lo);
        g_kp[((size_t)bkv * NDP_ + dp) * S_ + s0 + s] = make_uint2(hi, lo);
    }
}

// ---------------- V pack: f32 [bkv][S][HD] -> uint2 [bkv][spair][HD] ----------------
__global__ __launch_bounds__(256) void pack_v_kernel() {
    int idx = blockIdx.x * 256 + threadIdx.x;
    const int total = B_ * NKV_ * (S_ / 2) * HD_;
    if (idx >= total) return;
    int d = idx % HD_;
    int sp = (idx / HD_) % (S_ / 2);
    int bkv = idx / (HD_ * (S_ / 2));
    const float* vb = g_v + ((size_t)bkv * S_ + 2 * sp) * HD_ + d;
    uint32_t hi, lo;
    split_pack(vb[0], vb[HD_], hi, lo);
    g_vp[idx] = make_uint2(hi, lo);
}

// ---------------- MODE 0 epilogue scatter (coalesced f32, pairs) ----------------
__device__ __forceinline__ void emit_qkv(int row, int col, float v0, float v1) {
    int b = row >> 11, s = row & (S_ - 1);
    if (col < NH_ * HD_) {
        int h = col / HD_, d = col % HD_;
        float* p = &g_q[((size_t)(b * NH_ + h) * S_ + s) * HD_ + d];
        p[0] = v0 * g_qscale[d];
        p[1] = v1 * g_qscale[d + 1];
    } else if (col < NH_ * HD_ + NKV_ * HD_) {
        int cc = col - NH_ * HD_;
        int h = cc / HD_, d = cc % HD_;
        float* p = &g_k[((size_t)(b * NKV_ + h) * S_ + s) * HD_ + d];
        p[0] = v0; p[1] = v1;
    } else {
        int cc = col - NH_ * HD_ - NKV_ * HD_;
        int h = cc / HD_, d = cc % HD_;
        float* p = &g_v[((size_t)(b * NKV_ + h) * S_ + s) * HD_ + d];
        p[0] = v0; p[1] = v1;
    }
}

// ---------------- tensor-core GEMM, ping-pong smem ----------------
#define GSTRU 132   // uint2 stride; 132 % 16 == 4 -> conflict-free LDS.64

template <int MODE>
__global__ __launch_bounds__(256) void gemm_tc(
    const float* __restrict__ A_arg, const float* __restrict__ W,
    const float* __restrict__ bias, float* __restrict__ C, int N, int K)
{
    const float* A = (MODE == 1) ? (const float*)g_o : A_arg;

    __shared__ uint2 Asm[2][16][GSTRU];
    __shared__ uint2 Bsm[2][16][GSTRU];

    int tid = threadIdx.x;
    int lane = tid & 31, wid = tid >> 5;
    int g = lane >> 2, tig = lane & 3;
    int wm = wid >> 2, wn = wid & 3;
    int bm = blockIdx.y * 128, bn = blockIdx.x * 128;

    float acc[4][4][4];
#pragma unroll
    for (int mi = 0; mi < 4; mi++)
#pragma unroll
        for (int ni = 0; ni < 4; ni++)
#pragma unroll
            for (int c = 0; c < 4; c++) acc[mi][ni][c] = 0.0f;

    int r0 = tid >> 2;
    int c4 = (tid & 3) * 4;
    const float* Ab = A + (size_t)bm * K;
    const float* Wb = W + (size_t)bn * K;

    // copy tile t -> buffer bsel
    auto copy_tile = [&](int k0, int bsel) {
#pragma unroll
        for (int i = 0; i < 2; i++) {
            int rr = r0 + i * 64;
#pragma unroll
            for (int j = 0; j < 2; j++) {
                float4 va = *(const float4*)&Ab[(size_t)rr * K + k0 + c4 + j * 16];
                float4 vb = *(const float4*)&Wb[(size_t)rr * K + k0 + c4 + j * 16];
                int kp = (c4 >> 1) + j * 8;
                uint32_t hi, lo;
                split_pack(va.x, va.y, hi, lo); Asm[bsel][kp][rr] = make_uint2(hi, lo);
                split_pack(va.z, va.w, hi, lo); Asm[bsel][kp + 1][rr] = make_uint2(hi, lo);
                split_pack(vb.x, vb.y, hi, lo); Bsm[bsel][kp][rr] = make_uint2(hi, lo);
                split_pack(vb.z, vb.w, hi, lo); Bsm[bsel][kp + 1][rr] = make_uint2(hi, lo);
            }
        }
    };

    copy_tile(0, 0);

    int nk = K >> 5;
    for (int t = 0; t < nk; t++) {
        __syncthreads();
        if (t + 1 < nk) copy_tile((t + 1) << 5, (t + 1) & 1);
        int cur = t & 1;

#pragma unroll
        for (int ks = 0; ks < 2; ks++) {
            int kp0 = ks * 8;
            uint32_t afh[4][4], afl[4][4], bfh[4][2], bfl[4][2];
#pragma unroll
            for (int mi = 0; mi < 4; mi++) {
                int m0 = wm * 64 + mi * 16;
                uint2 q0v = Asm[cur][kp0 + tig][m0 + g];
                uint2 q1v = Asm[cur][kp0 + tig][m0 + g + 8];
                uint2 q2v = Asm[cur][kp0 + tig + 4][m0 + g];
                uint2 q3v = Asm[cur][kp0 + tig + 4][m0 + g + 8];
                afh[mi][0] = q0v.x; afl[mi][0] = q0v.y;
                afh[mi][1] = q1v.x; afl[mi][1] = q1v.y;
                afh[mi][2] = q2v.x; afl[mi][2] = q2v.y;
                afh[mi][3] = q3v.x; afl[mi][3] = q3v.y;
            }
#pragma unroll
            for (int ni = 0; ni < 4; ni++) {
                int n0 = wn * 32 + ni * 8;
                uint2 b0v = Bsm[cur][kp0 + tig][n0 + g];
                uint2 b1v = Bsm[cur][kp0 + tig + 4][n0 + g];
                bfh[ni][0] = b0v.x; bfl[ni][0] = b0v.y;
                bfh[ni][1] = b1v.x; bfl[ni][1] = b1v.y;
            }
#pragma unroll
            for (int mi = 0; mi < 4; mi++)
#pragma unroll
                for (int ni = 0; ni < 4; ni++)
                    mma3(acc[mi][ni], afh[mi], afl[mi], bfh[ni], bfl[ni]);
        }
    }

#pragma unroll
    for (int mi = 0; mi < 4; mi++) {
#pragma unroll
        for (int ni = 0; ni < 4; ni++) {
            int row0 = bm + wm * 64 + mi * 16 + g;
            int col0 = bn + wn * 32 + ni * 8 + tig * 2;
            float b0 = bias[col0], b1 = bias[col0 + 1];
            float v00 = acc[mi][ni][0] + b0, v01 = acc[mi][ni][1] + b1;
            float v10 = acc[mi][ni][2] + b0, v11 = acc[mi][ni][3] + b1;
            if (MODE == 0) {
                emit_qkv(row0, col0, v00, v01);
                emit_qkv(row0 + 8, col0, v10, v11);
            } else {
                C[(size_t)row0 * N + col0] = v00;
                C[(size_t)row0 * N + col0 + 1] = v01;
                C[(size_t)(row0 + 8) * N + col0] = v10;
                C[(size_t)(row0 + 8) * N + col0 + 1] = v11;
            }
        }
    }
}

// ---------------- warp-owns-row flash attention, BR=128, BC=64, ping-pong K/V ----------------
#define BR_ 128
#define BC_ 64

struct AttnSmem {
    uint2 Qp[NDP_][132];          // [dpair][qrow 0..127]
    uint2 Kp[2][NDP_][68];        // [buf][dpair][kvcol 0..63]
    uint2 Vp[2][BC_ / 2][84];     // [buf][spair][d 0..79]
};

__global__ __launch_bounds__(256) void attn_kernel() {
    extern __shared__ char smem_raw[];
    AttnSmem& sm = *reinterpret_cast<AttnSmem*>(smem_raw);

    int tid = threadIdx.x;
    int lane = tid & 31, wid = tid >> 5;
    int g = lane >> 2, tig = lane & 3;
    int qt = gridDim.x - 1 - blockIdx.x;   // long blocks first
    int bh = blockIdx.y;
    int b = bh / NH_, h = bh % NH_;
    int kvh = h / GQA_G_;
    int bkv = b * NKV_ + kvh;
    int q0 = qt * BR_;

    const uint2* ksrc = g_kp + (size_t)bkv * NDP_ * S_;
    const uint2* vsrc = g_vp + (size_t)bkv * (S_ / 2) * HD_;

    // copy K/V tile (k0) into buffer bsel: 2560 float4 across 256 threads
    auto copy_kv = [&](int k0, int bsel) {
        for (int i = tid; i < 1280; i += 256) {
            int dp = i >> 5, c2 = (i & 31) * 2;
            *(float4*)&sm.Kp[bsel][dp][c2] =
                *(const float4*)&ksrc[(size_t)dp * S_ + k0 + c2];
        }
        for (int i = tid; i < 1280; i += 256) {
            int sp = i / 40, c2 = (i % 40) * 2;
            *(float4*)&sm.Vp[bsel][sp][c2] =
                *(const float4*)&vsrc[(size_t)(k0 / 2 + sp) * HD_ + c2];
        }
    };

    // Q fill (split f32 -> packed) once
    const float* qptr = g_q + ((size_t)bh * S_ + q0) * HD_;
    for (int i = tid; i < BR_ * (HD_ / 4); i += 256) {
        int r = i / 20, c4 = (i % 20) * 4;
        float4 qv = *(const float4*)&qptr[(size_t)r * HD_ + c4];
        uint32_t hi, lo;
        split_pack(qv.x, qv.y, hi, lo); sm.Qp[c4 >> 1][r] = make_uint2(hi, lo);
        split_pack(qv.z, qv.w, hi, lo); sm.Qp[(c4 >> 1) + 1][r] = make_uint2(hi, lo);
    }
    copy_kv(0, 0);

    float accO[10][4];
#pragma unroll
    for (int ni = 0; ni < 10; ni++)
#pragma unroll
        for (int c = 0; c < 4; c++) accO[ni][c] = 0.0f;

    int m0 = wid * 16;
    int row0 = m0 + g, row1 = row0 + 8;        // local q rows
    int qrow0 = q0 + row0, qrow1 = q0 + row1;  // global
    int warp_max_row = q0 + m0 + 15;
    float m0r = -3.0e38f, m1r = -3.0e38f, l0r = 0.0f, l1r = 0.0f;

    int nkt = 2 * qt + 2;
    for (int kt = 0; kt < nkt; kt++) {
        int k0 = kt * BC_;
        __syncthreads();                        // buf[kt&1] ready; prior readers of buf[(kt+1)&1] done
        if (kt + 1 < nkt) copy_kv(k0 + BC_, (kt + 1) & 1);
        int cur = kt & 1;

        if (k0 <= warp_max_row) {               // tile not fully masked for this warp
            // ---- S = Q K^T: warp tile 16 x 64 ----
            float sf[8][4];
#pragma unroll
            for (int ni = 0; ni < 8; ni++)
#pragma unroll
                for (int c = 0; c < 4; c++) sf[ni][c] = 0.0f;

#pragma unroll
            for (int ks = 0; ks < 5; ks++) {
                int kp0 = ks * 8;
                uint2 q0v = sm.Qp[kp0 + tig][m0 + g];
                uint2 q1v = sm.Qp[kp0 + tig][m0 + g + 8];
                uint2 q2v = sm.Qp[kp0 + tig + 4][m0 + g];
                uint2 q3v = sm.Qp[kp0 + tig + 4][m0 + g + 8];
                uint32_t ah[4] = {q0v.x, q1v.x, q2v.x, q3v.x};
                uint32_t al[4] = {q0v.y, q1v.y, q2v.y, q3v.y};
#pragma unroll
                for (int ni = 0; ni < 8; ni++) {
                    uint2 b0v = sm.Kp[cur][kp0 + tig][ni * 8 + g];
                    uint2 b1v = sm.Kp[cur][kp0 + tig + 4][ni * 8 + g];
                    uint32_t bh2[2] = {b0v.x, b1v.x}, bl2[2] = {b0v.y, b1v.y};
                    mma3(sf[ni], ah, al, bh2, bl2);
                }
            }

            // ---- causal mask (partial tiles only) ----
            if (k0 + BC_ - 1 > qrow0) {
#pragma unroll
                for (int ni = 0; ni < 8; ni++) {
                    int nb = k0 + ni * 8 + 2 * tig;
                    if (nb > qrow0)     sf[ni][0] = -3.0e38f;
                    if (nb + 1 > qrow0) sf[ni][1] = -3.0e38f;
                    if (nb > qrow1)     sf[ni][2] = -3.0e38f;
                    if (nb + 1 > qrow1) sf[ni][3] = -3.0e38f;
                }
            }

            // ---- warp-local online softmax ----
            float pm0 = -3.0e38f, pm1 = -3.0e38f;
#pragma unroll
            for (int ni = 0; ni < 8; ni++) {
                pm0 = fmaxf(pm0, fmaxf(sf[ni][0], sf[ni][1]));
                pm1 = fmaxf(pm1, fmaxf(sf[ni][2], sf[ni][3]));
            }
            pm0 = fmaxf(pm0, __shfl_xor_sync(0xffffffffu, pm0, 1));
            pm0 = fmaxf(pm0, __shfl_xor_sync(0xffffffffu, pm0, 2));
            pm1 = fmaxf(pm1, __shfl_xor_sync(0xffffffffu, pm1, 1));
            pm1 = fmaxf(pm1, __shfl_xor_sync(0xffffffffu, pm1, 2));
            float mn0 = fmaxf(m0r, pm0), mn1 = fmaxf(m1r, pm1);
            float a0 = __expf(m0r - mn0), a1 = __expf(m1r - mn1);
            m0r = mn0; m1r = mn1;

            float ps0 = 0.0f, ps1 = 0.0f;
#pragma unroll
            for (int ni = 0; ni < 8; ni++) {
                sf[ni][0] = __expf(sf[ni][0] - mn0);
                sf[ni][1] = __expf(sf[ni][1] - mn0);
                sf[ni][2] = __expf(sf[ni][2] - mn1);
                sf[ni][3] = __expf(sf[ni][3] - mn1);
                ps0 += sf[ni][0] + sf[ni][1];
                ps1 += sf[ni][2] + sf[ni][3];
            }
            ps0 += __shfl_xor_sync(0xffffffffu, ps0, 1);
            ps0 += __shfl_xor_sync(0xffffffffu, ps0, 2);
            ps1 += __shfl_xor_sync(0xffffffffu, ps1, 1);
            ps1 += __shfl_xor_sync(0xffffffffu, ps1, 2);
            l0r = l0r * a0 + ps0;
            l1r = l1r * a1 + ps1;

            // ---- rescale accO; O += P V over full 64 kv cols ----
#pragma unroll
            for (int ni = 0; ni < 10; ni++) {
                accO[ni][0] *= a0; accO[ni][1] *= a0;
                accO[ni][2] *= a1; accO[ni][3] *= a1;
            }
#pragma unroll
            for (int kc = 0; kc < 4; kc++) {
                uint32_t ah[4], al[4];
                split_pack(sf[2 * kc][0],     sf[2 * kc][1],     ah[0], al[0]);
                split_pack(sf[2 * kc][2],     sf[2 * kc][3],     ah[1], al[1]);
                split_pack(sf[2 * kc + 1][0], sf[2 * kc + 1][1], ah[2], al[2]);
                split_pack(sf[2 * kc + 1][2], sf[2 * kc + 1][3], ah[3], al[3]);
                int kb = kc * 8;
#pragma unroll
                for (int ni = 0; ni < 10; ni++) {
                    uint2 b0v = sm.Vp[cur][kb + tig][ni * 8 + g];
                    uint2 b1v = sm.Vp[cur][kb + tig + 4][ni * 8 + g];
                    uint32_t bh2[2] = {b0v.x, b1v.x}, bl2[2] = {b0v.y, b1v.y};
                    mma3(accO[ni], ah, al, bh2, bl2);
                }
            }
        }
    }

    // ---- normalize + write (warp-local, no merge needed) ----
    float li0 = 1.0f / l0r, li1 = 1.0f / l1r;
    float* o0 = g_o + ((size_t)(b * S_) + qrow0) * HID_ + h * HD_;
    float* o1 = g_o + ((size_t)(b * S_) + qrow1) * HID_ + h * HD_;
#pragma unroll
    for (int ni = 0; ni < 10; ni++) {
        int d = ni * 8 + 2 * tig;
        o0[d]     = accO[ni][0] * li0;
        o0[d + 1] = accO[ni][1] * li0;
        o1[d]     = accO[ni][2] * li1;
        o1[d + 1] = accO[ni][3] * li1;
    }
}

// ---------------- launch ----------------
extern "C" void kernel_launch(void* const* d_in, const int* in_sizes, int n_in,
                              void* d_out, int out_size) {
    const float* hs      = (const float*)d_in[0];
    const float* scaling = (const float*)d_in[2];
    const float* qkv_w   = (const float*)d_in[3];
    const float* qkv_b   = (const float*)d_in[4];
    const float* o_w     = (const float*)d_in[5];
    const float* o_b     = (const float*)d_in[6];
    float* out = (float*)d_out;

    const int attn_smem = (int)sizeof(AttnSmem);
    cudaFuncSetAttribute(attn_kernel, cudaFuncAttributeMaxDynamicSharedMemorySize, attn_smem);

    qscale_kernel<<<1, 128>>>(scaling);

    dim3 g1(QKV_DIM_ / 128, M_TOT_ / 128);
    gemm_tc<0><<<g1, 256>>>(hs, qkv_w, qkv_b, nullptr, QKV_DIM_, HID_);

    dim3 gk(S_ / 64, B_ * NKV_);
    pack_k_kernel<<<gk, 256>>>();
    const int vtot = B_ * NKV_ * (S_ / 2) * HD_;
    pack_v_kernel<<<(vtot + 255) / 256, 256>>>();

    dim3 ga(S_ / BR_, B_ * NH_);
    attn_kernel<<<ga, 256, attn_smem>>>();

    dim3 g3(HID_ / 128, M_TOT_ / 128);
    gemm_tc<1><<<g3, 256>>>(nullptr, o_w, o_b, out, HID_, HID_);
}